// round 14
// baseline (speedup 1.0000x reference)
#include <cuda_runtime.h>
#include <cuda_bf16.h>
#include <cuda_fp16.h>
#include <math.h>
#include <stdint.h>

#define NN 50000
#define EE 800000
#define ET 850000
#define CC 64
#define HC 128
#define NCLS 4
#define EPS_GN 1e-5f
#define SCAN_B 1024
#define SCAN_NB ((NN + SCAN_B - 1) / SCAN_B)
#define PADN 50048            /* 391 * 128 */
#define GEMM_CTAS (PADN / 128)
#define ASTR 40               /* A smem row stride (elems): conflict-free ldmatrix */
#define WSTR 136              /* W smem row stride (elems): conflict-free ldmatrix */

#define ATILE (128 * ASTR * 2)     /* bytes per A split tile: 10240 */
#define WTILE (32 * WSTR * 2)      /* bytes per W split tile: 8704 */
#define ABUF  (ATILE * 2)          /* hi+lo */
#define WBUF  (WTILE * 2)
#define SMEM_W_OFF (ABUF * 2)
#define SMEM_TOT (ABUF * 2 + WBUF * 2)   /* 75776 */

// ---------------- mma / cp.async helpers (base-target PTX: sm_80+) ----------------
__device__ __forceinline__ uint32_t smem_u32(const void* p) {
    uint32_t a;
    asm("{ .reg .u64 t; cvta.to.shared.u64 t, %1; cvt.u32.u64 %0, t; }" : "=r"(a) : "l"(p));
    return a;
}
__device__ __forceinline__ void ldsm_x4(uint32_t& r0, uint32_t& r1, uint32_t& r2, uint32_t& r3, uint32_t addr) {
    asm volatile("ldmatrix.sync.aligned.m8n8.x4.shared.b16 {%0,%1,%2,%3}, [%4];"
                 : "=r"(r0), "=r"(r1), "=r"(r2), "=r"(r3) : "r"(addr));
}
__device__ __forceinline__ void ldsm_x4_t(uint32_t& r0, uint32_t& r1, uint32_t& r2, uint32_t& r3, uint32_t addr) {
    asm volatile("ldmatrix.sync.aligned.m8n8.x4.trans.shared.b16 {%0,%1,%2,%3}, [%4];"
                 : "=r"(r0), "=r"(r1), "=r"(r2), "=r"(r3) : "r"(addr));
}
__device__ __forceinline__ void mma_bf16(float* c, const uint32_t* a, const uint32_t* b) {
    asm volatile("mma.sync.aligned.m16n8k16.row.col.f32.bf16.bf16.f32 "
                 "{%0,%1,%2,%3}, {%4,%5,%6,%7}, {%8,%9}, {%0,%1,%2,%3};"
                 : "+f"(c[0]), "+f"(c[1]), "+f"(c[2]), "+f"(c[3])
                 : "r"(a[0]), "r"(a[1]), "r"(a[2]), "r"(a[3]), "r"(b[0]), "r"(b[1]));
}
__device__ __forceinline__ void cp16(uint32_t dst, const void* src) {
    asm volatile("cp.async.cg.shared.global [%0], [%1], 16;" :: "r"(dst), "l"(src));
}
#define CP_COMMIT() asm volatile("cp.async.commit_group;" ::: "memory")
#define CP_WAIT1()  asm volatile("cp.async.wait_group 1;" ::: "memory")
#define CP_WAIT0()  asm volatile("cp.async.wait_group 0;" ::: "memory")

// ---------------- scratch ----------------
__device__ __align__(16) __half g_xlh[NN * HC];   /* fp16 source-transform (attention gather payload) */
__device__ __align__(16) float g_xr[NN * HC];
__device__ __align__(16) float g_h[NN * CC];
__device__ __align__(16) __nv_bfloat16 g_Ah[PADN * HC];
__device__ __align__(16) __nv_bfloat16 g_Al[PADN * HC];
__device__ __align__(16) __nv_bfloat16 g_Blh[HC * HC], g_Bll[HC * HC];
__device__ __align__(16) __nv_bfloat16 g_Brh[HC * HC], g_Brl[HC * HC];
__device__ __align__(16) int   g_deg[NN];
__device__ int   g_rowptr[NN + 1];
__device__ int   g_cursor[NN];
__device__ int   g_csrc[ET];
__device__ int   g_scanval[64];
__device__ __align__(16) int g_scanflag[64];
__device__ float g_sum[CC], g_sumsq[CC];
__device__ __align__(16) float g_blf[HC], g_brf[HC];
__device__ float g_W1f[CC * NCLS], g_b1f[NCLS];

// ---------------- CSR build ----------------
__global__ void k_zero_deg() {
    int i = blockIdx.x * blockDim.x + threadIdx.x;
    int4 z = make_int4(0, 0, 0, 0);
    if (i < NN / 4) ((int4*)g_deg)[i] = z;
    if (i < 16)     ((int4*)g_scanflag)[i] = z;
}

__global__ void k_count(const int* __restrict__ ei) {
    int t = blockIdx.x * blockDim.x + threadIdx.x;
    if (t >= EE / 4) return;
    int4 d = ((const int4*)(ei + EE))[t];
    atomicAdd(&g_deg[d.x], 1);
    atomicAdd(&g_deg[d.y], 1);
    atomicAdd(&g_deg[d.z], 1);
    atomicAdd(&g_deg[d.w], 1);
}

__global__ void k_scan_chained() {
    __shared__ int sh[SCAN_B];
    __shared__ int s_prefix;
    int b = blockIdx.x, tid = threadIdx.x;
    int i = b * SCAN_B + tid;
    int v = (i < NN) ? (g_deg[i] + 1) : 0;
    sh[tid] = v;
    __syncthreads();
#pragma unroll
    for (int off = 1; off < SCAN_B; off <<= 1) {
        int t = (tid >= off) ? sh[tid - off] : 0;
        __syncthreads();
        sh[tid] += t;
        __syncthreads();
    }
    if (tid == 0) {
        int prefix = 0;
        if (b > 0) {
            while (atomicAdd(&g_scanflag[b - 1], 0) == 0) { }
            prefix = g_scanval[b - 1];
        }
        s_prefix = prefix;
        g_scanval[b] = prefix + sh[SCAN_B - 1];
        __threadfence();
        atomicExch(&g_scanflag[b], 1);
        if (b == SCAN_NB - 1) g_rowptr[NN] = prefix + sh[SCAN_B - 1];
    }
    __syncthreads();
    if (i < NN) {
        int excl = s_prefix + sh[tid] - v;
        g_rowptr[i] = excl;
        g_cursor[i] = excl;
    }
    if (b == 0 && tid < CC) { g_sum[tid] = 0.0f; g_sumsq[tid] = 0.0f; }
}

__global__ void k_scatter(const int* __restrict__ ei) {
    int t = blockIdx.x * blockDim.x + threadIdx.x;
    if (t < EE / 4) {
        int4 s = ((const int4*)ei)[t];
        int4 d = ((const int4*)(ei + EE))[t];
        int p;
        p = atomicAdd(&g_cursor[d.x], 1); g_csrc[p] = s.x;
        p = atomicAdd(&g_cursor[d.y], 1); g_csrc[p] = s.y;
        p = atomicAdd(&g_cursor[d.z], 1); g_csrc[p] = s.z;
        p = atomicAdd(&g_cursor[d.w], 1); g_csrc[p] = s.w;
    } else {
        int base = (t - EE / 4) * 4;
#pragma unroll
        for (int j = 0; j < 4; j++) {
            int i = base + j;
            if (i < NN) {
                int p = atomicAdd(&g_cursor[i], 1);
                g_csrc[p] = i;
            }
        }
    }
}

// ---------------- fp32 -> (hi, lo) bf16 split ----------------
__device__ __forceinline__ void split_bf16(float x, __nv_bfloat16& hi, __nv_bfloat16& lo) {
    hi = __float2bfloat16(x);
    lo = __float2bfloat16(x - __bfloat162float(hi));
}

__global__ void k_conv_x(const float* __restrict__ x) {
    int t = blockIdx.x * blockDim.x + threadIdx.x;
    if (t >= PADN * 32) return;
    int row = t >> 5;
    int c4 = (t & 31) * 4;
    float4 v = make_float4(0.f, 0.f, 0.f, 0.f);
    if (row < NN) v = *(const float4*)(x + row * HC + c4);
    __nv_bfloat16 h0, h1, h2, h3, l0, l1, l2, l3;
    split_bf16(v.x, h0, l0); split_bf16(v.y, h1, l1);
    split_bf16(v.z, h2, l2); split_bf16(v.w, h3, l3);
    __nv_bfloat162* ph = (__nv_bfloat162*)(g_Ah + row * HC + c4);
    __nv_bfloat162* pl = (__nv_bfloat162*)(g_Al + row * HC + c4);
    ph[0] = __nv_bfloat162(h0, h1); ph[1] = __nv_bfloat162(h2, h3);
    pl[0] = __nv_bfloat162(l0, l1); pl[1] = __nv_bfloat162(l2, l3);
}

__global__ void k_conv_w1(const float* __restrict__ Wl, const float* __restrict__ Wr) {
    int t = blockIdx.x * blockDim.x + threadIdx.x;
    if (t >= 2 * HC * HC) return;
    int which = t >> 14;
    int r = t & 16383;
    const float* W = which ? Wr : Wl;
    __nv_bfloat16 *Bh = which ? g_Brh : g_Blh, *Bl = which ? g_Brl : g_Bll;
    __nv_bfloat16 hi, lo;
    split_bf16(W[r], hi, lo);
    Bh[r] = hi;
    Bl[r] = lo;
}

// ---------------- split-bf16 tensor-core GEMM, cp.async double-buffered ----------------
// blockIdx.y==0 -> xl path (fp16 output); ==1 -> xr path (fp32 output)
template<int K>
__global__ void __launch_bounds__(256, 2)
k_mma_gemm(const __nv_bfloat16* __restrict__ Ah, const __nv_bfloat16* __restrict__ Al,
           const __nv_bfloat16* __restrict__ Blh, const __nv_bfloat16* __restrict__ Bll,
           const __nv_bfloat16* __restrict__ Brh, const __nv_bfloat16* __restrict__ Brl,
           const float* __restrict__ bl, const float* __restrict__ br,
           __half* __restrict__ outl, float* __restrict__ outr) {
    extern __shared__ char smem[];
    uint32_t sbase = smem_u32(smem);
    const __nv_bfloat16* Bh = blockIdx.y ? Brh : Blh;
    const __nv_bfloat16* Bl = blockIdx.y ? Brl : Bll;
    const float* bias = blockIdx.y ? br : bl;

    int tid = threadIdx.x;
    int wid = tid >> 5, lane = tid & 31;
    int wr = wid & 3;
    int wc = wid >> 2;
    int row0 = blockIdx.x * 128;
    constexpr int T = K / 32;

    float acc[2][8][4];
#pragma unroll
    for (int m = 0; m < 2; m++)
#pragma unroll
        for (int n = 0; n < 8; n++)
#pragma unroll
            for (int q = 0; q < 4; q++) acc[m][n][q] = 0.0f;

#define LOAD_TILE(kt, buf) do {                                               \
        int k0_ = (kt) * 32;                                                  \
        uint32_t ab_ = sbase + (buf) * ABUF;                                  \
        uint32_t wb_ = sbase + SMEM_W_OFF + (buf) * WBUF;                     \
        _Pragma("unroll")                                                     \
        for (int i_ = 0; i_ < 2; i_++) {                                      \
            int id_ = tid + i_ * 256;                                         \
            int r_ = id_ >> 2, c8_ = (id_ & 3) * 8;                           \
            size_t go_ = (size_t)(row0 + r_) * K + k0_ + c8_;                 \
            cp16(ab_ + (r_ * ASTR + c8_) * 2, Ah + go_);                      \
            cp16(ab_ + ATILE + (r_ * ASTR + c8_) * 2, Al + go_);              \
        }                                                                     \
        _Pragma("unroll")                                                     \
        for (int i_ = 0; i_ < 2; i_++) {                                      \
            int id_ = tid + i_ * 256;                                         \
            int kk_ = id_ >> 4, n8_ = (id_ & 15) * 8;                         \
            int go_ = (k0_ + kk_) * 128 + n8_;                                \
            cp16(wb_ + (kk_ * WSTR + n8_) * 2, Bh + go_);                     \
            cp16(wb_ + WTILE + (kk_ * WSTR + n8_) * 2, Bl + go_);             \
        }                                                                     \
    } while (0)

    LOAD_TILE(0, 0);
    CP_COMMIT();

#pragma unroll
    for (int kt = 0; kt < T; kt++) {
        int buf = kt & 1;
        if (kt + 1 < T) {
            LOAD_TILE(kt + 1, (kt + 1) & 1);
            CP_COMMIT();
            CP_WAIT1();
        } else {
            CP_WAIT0();
        }
        __syncthreads();
        uint32_t aHB = sbase + buf * ABUF;
        uint32_t aLB = aHB + ATILE;
        uint32_t wHB = sbase + SMEM_W_OFF + buf * WBUF;
        uint32_t wLB = wHB + WTILE;
#pragma unroll
        for (int kk = 0; kk < 32; kk += 16) {
            uint32_t ah[2][4], al[2][4];
#pragma unroll
            for (int m = 0; m < 2; m++) {
                int arow = wr * 32 + m * 16 + (lane & 15);
                int acol = kk + (lane >> 4) * 8;
                uint32_t off = (uint32_t)(arow * ASTR + acol) * 2;
                ldsm_x4(ah[m][0], ah[m][1], ah[m][2], ah[m][3], aHB + off);
                ldsm_x4(al[m][0], al[m][1], al[m][2], al[m][3], aLB + off);
            }
#pragma unroll
            for (int np = 0; np < 4; np++) {
                int krow = kk + (lane & 7) + ((lane >> 3) & 1) * 8;
                int ncol = wc * 64 + np * 16 + (lane >> 4) * 8;
                uint32_t off = (uint32_t)(krow * WSTR + ncol) * 2;
                uint32_t bh[4], blo[4];
                ldsm_x4_t(bh[0], bh[1], bh[2], bh[3], wHB + off);
                ldsm_x4_t(blo[0], blo[1], blo[2], blo[3], wLB + off);
#pragma unroll
                for (int m = 0; m < 2; m++) {
#pragma unroll
                    for (int nn = 0; nn < 2; nn++) {
                        float* c = acc[m][np * 2 + nn];
                        mma_bf16(c, ah[m], &bh[nn * 2]);
                        mma_bf16(c, ah[m], &blo[nn * 2]);
                        mma_bf16(c, al[m], &bh[nn * 2]);
                    }
                }
            }
        }
        __syncthreads();
    }
#undef LOAD_TILE

    // epilogue: xl path stores fp16, xr path fp32
    int rb = row0 + wr * 32 + (lane >> 2);
    int cb = wc * 64 + (lane & 3) * 2;
    bool is_r = blockIdx.y != 0;
#pragma unroll
    for (int m = 0; m < 2; m++) {
#pragma unroll
        for (int nt = 0; nt < 8; nt++) {
            int cc0 = cb + nt * 8;
            float b0 = __ldg(bias + cc0), b1 = __ldg(bias + cc0 + 1);
            int r1 = rb + m * 16;
            int r2 = r1 + 8;
            if (r1 < NN) {
                float p0 = acc[m][nt][0] + b0, p1 = acc[m][nt][1] + b1;
                if (is_r) *(float2*)(outr + (size_t)r1 * HC + cc0) = make_float2(p0, p1);
                else      *(__half2*)(outl + (size_t)r1 * HC + cc0) = __floats2half2_rn(p0, p1);
            }
            if (r2 < NN) {
                float p0 = acc[m][nt][2] + b0, p1 = acc[m][nt][3] + b1;
                if (is_r) *(float2*)(outr + (size_t)r2 * HC + cc0) = make_float2(p0, p1);
                else      *(__half2*)(outl + (size_t)r2 * HC + cc0) = __floats2half2_rn(p0, p1);
            }
        }
    }
}

// ---- fused attention + softmax (shift-invariant, no max pass) + aggregation ----
// + GraphNorm stats + bf16 split of h.  warp per node, 2-edge software pipeline.
// xl gathered in fp16 (half the L2 traffic); xr per-node in fp32.
__global__ void k_attn_agg(const __half* __restrict__ xl, const float* __restrict__ xr,
                           const float* __restrict__ att, const float* __restrict__ bias) {
    __shared__ float s_sum[CC], s_sq[CC];
    int tid = threadIdx.x;
    if (tid < CC) { s_sum[tid] = 0.0f; s_sq[tid] = 0.0f; }
    __syncthreads();

    int node = (blockIdx.x * blockDim.x + tid) >> 5;
    int lane = tid & 31;
    bool active = node < NN;
    int s0 = 0, s1 = 0;
    if (active) { s0 = g_rowptr[node]; s1 = g_rowptr[node + 1]; }
    float4 t4 = *(const float4*)(att + lane * 4);
    float4 xq = make_float4(0.f, 0.f, 0.f, 0.f);
    if (active) xq = *(const float4*)(xr + node * HC + lane * 4);

    float denom = 0.0f;
    float a0 = 0.0f, a1 = 0.0f, a2 = 0.0f, a3 = 0.0f;

#define GATHER(i, vv) do {                                                       \
        int sn_ = __ldg(&g_csrc[i]);                                             \
        uint2 raw_ = *(const uint2*)(xl + (size_t)sn_ * HC + lane * 4);          \
        float2 f01_ = __half22float2(*(__half2*)&raw_.x);                        \
        float2 f23_ = __half22float2(*(__half2*)&raw_.y);                        \
        vv = make_float4(f01_.x, f01_.y, f23_.x, f23_.y);                        \
    } while (0)

#define DOTP(vv, pp) do {                                   \
        float m_;                                            \
        pp = 0.0f;                                           \
        m_ = vv.x + xq.x; pp += fmaxf(m_, 0.2f * m_) * t4.x; \
        m_ = vv.y + xq.y; pp += fmaxf(m_, 0.2f * m_) * t4.y; \
        m_ = vv.z + xq.z; pp += fmaxf(m_, 0.2f * m_) * t4.z; \
        m_ = vv.w + xq.w; pp += fmaxf(m_, 0.2f * m_) * t4.w; \
    } while (0)

    int idx = s0;
    float4 v0 = make_float4(0.f, 0.f, 0.f, 0.f);
    float4 v1 = v0;
    if (idx < s1)     GATHER(idx, v0);
    if (idx + 1 < s1) GATHER(idx + 1, v1);
    for (; idx + 1 < s1; idx += 2) {
        float4 c0 = v0, c1 = v1;
        if (idx + 2 < s1) GATHER(idx + 2, v0);
        if (idx + 3 < s1) GATHER(idx + 3, v1);
        float pa, pb;
        DOTP(c0, pa);
        DOTP(c1, pb);
        pa += __shfl_xor_sync(0xffffffffu, pa, 8);
        pb += __shfl_xor_sync(0xffffffffu, pb, 8);
        pa += __shfl_xor_sync(0xffffffffu, pa, 4);
        pb += __shfl_xor_sync(0xffffffffu, pb, 4);
        pa += __shfl_xor_sync(0xffffffffu, pa, 2);
        pb += __shfl_xor_sync(0xffffffffu, pb, 2);
        pa += __shfl_xor_sync(0xffffffffu, pa, 1);
        pb += __shfl_xor_sync(0xffffffffu, pb, 1);
        float wa = __expf(pa), wb = __expf(pb);
        a0 += wa * c0.x + wb * c1.x;
        a1 += wa * c0.y + wb * c1.y;
        a2 += wa * c0.z + wb * c1.z;
        a3 += wa * c0.w + wb * c1.w;
        denom += wa + wb;
    }
    if (idx < s1) {                     // odd tail
        float p;
        DOTP(v0, p);
        p += __shfl_xor_sync(0xffffffffu, p, 8);
        p += __shfl_xor_sync(0xffffffffu, p, 4);
        p += __shfl_xor_sync(0xffffffffu, p, 2);
        p += __shfl_xor_sync(0xffffffffu, p, 1);
        float w = __expf(p);
        a0 += w * v0.x;
        a1 += w * v0.y;
        a2 += w * v0.z;
        a3 += w * v0.w;
        denom += w;
    }
#undef DOTP
#undef GATHER

    float inv = 1.0f / (denom + 1e-16f);
    a0 *= inv; a1 *= inv; a2 *= inv; a3 *= inv;
    a0 = 0.5f * (a0 + __shfl_down_sync(0xffffffffu, a0, 16));
    a1 = 0.5f * (a1 + __shfl_down_sync(0xffffffffu, a1, 16));
    a2 = 0.5f * (a2 + __shfl_down_sync(0xffffffffu, a2, 16));
    a3 = 0.5f * (a3 + __shfl_down_sync(0xffffffffu, a3, 16));
    if (active && lane < 16) {
        float4 bb = *(const float4*)(bias + lane * 4);
        float4 o;
        o.x = a0 + bb.x; o.y = a1 + bb.y; o.z = a2 + bb.z; o.w = a3 + bb.w;
        *(float4*)(g_h + node * CC + lane * 4) = o;
        __nv_bfloat16 h0, h1, h2, h3, l0, l1, l2, l3;
        split_bf16(o.x, h0, l0); split_bf16(o.y, h1, l1);
        split_bf16(o.z, h2, l2); split_bf16(o.w, h3, l3);
        __nv_bfloat162* ph = (__nv_bfloat162*)(g_Ah + node * CC + lane * 4);
        __nv_bfloat162* pl = (__nv_bfloat162*)(g_Al + node * CC + lane * 4);
        ph[0] = __nv_bfloat162(h0, h1); ph[1] = __nv_bfloat162(h2, h3);
        pl[0] = __nv_bfloat162(l0, l1); pl[1] = __nv_bfloat162(l2, l3);
        int c4 = lane * 4;
        atomicAdd(&s_sum[c4 + 0], o.x); atomicAdd(&s_sq[c4 + 0], o.x * o.x);
        atomicAdd(&s_sum[c4 + 1], o.y); atomicAdd(&s_sq[c4 + 1], o.y * o.y);
        atomicAdd(&s_sum[c4 + 2], o.z); atomicAdd(&s_sq[c4 + 2], o.z * o.z);
        atomicAdd(&s_sum[c4 + 3], o.w); atomicAdd(&s_sq[c4 + 3], o.w * o.w);
    }
    __syncthreads();
    if (tid < CC) {
        atomicAdd(&g_sum[tid], s_sum[tid]);
        atomicAdd(&g_sumsq[tid], s_sq[tid]);
    }
}

// ---- GraphNorm finalize + fold into layer-2 weights (splits stay [k][n]) ----
__global__ void k_finalize_fold2(const float* __restrict__ gamma,
                                 const float* __restrict__ beta,
                                 const float* __restrict__ a,
                                 const float* __restrict__ Wl, const float* __restrict__ bl,
                                 const float* __restrict__ Wr, const float* __restrict__ br) {
    __shared__ float s_scale[CC], s_shift[CC];
    int tid = threadIdx.x;
    if (tid < CC) {
        float mean = g_sum[tid] * (1.0f / NN);
        float ex2  = g_sumsq[tid] * (1.0f / NN);
        float ac = a[tid];
        float var = ex2 - 2.0f * ac * mean * mean + ac * ac * mean * mean;
        float r = rsqrtf(var + EPS_GN);
        float sc = gamma[tid] * r;
        s_scale[tid] = sc;
        s_shift[tid] = beta[tid] - sc * ac * mean;
        g_sum[tid] = 0.0f;
        g_sumsq[tid] = 0.0f;
    }
    __syncthreads();
    int j = tid & 127;
    int which = tid >> 7;
    const float* W = which ? Wr : Wl;
    const float* b = which ? br : bl;
    __nv_bfloat16* Bh = which ? g_Brh : g_Blh;
    __nv_bfloat16* Bl = which ? g_Brl : g_Bll;
    float* bf = which ? g_brf : g_blf;
    float acc = b[j];
#pragma unroll 8
    for (int k = 0; k < CC; k++) {
        float w = W[k * 128 + j];
        float wf = s_scale[k] * w;
        __nv_bfloat16 hi, lo;
        split_bf16(wf, hi, lo);
        Bh[k * 128 + j] = hi;
        Bl[k * 128 + j] = lo;
        acc += s_shift[k] * w;
    }
    bf[j] = acc;
}

__global__ void k_finalize_fold_final(const float* __restrict__ gamma,
                                      const float* __restrict__ beta,
                                      const float* __restrict__ a,
                                      const float* __restrict__ W1, const float* __restrict__ b1) {
    __shared__ float s_scale[CC], s_shift[CC];
    int tid = threadIdx.x;
    if (tid < CC) {
        float mean = g_sum[tid] * (1.0f / NN);
        float ex2  = g_sumsq[tid] * (1.0f / NN);
        float ac = a[tid];
        float var = ex2 - 2.0f * ac * mean * mean + ac * ac * mean * mean;
        float r = rsqrtf(var + EPS_GN);
        float sc = gamma[tid] * r;
        s_scale[tid] = sc;
        s_shift[tid] = beta[tid] - sc * ac * mean;
    }
    __syncthreads();
    if (tid < NCLS) {
        float acc = b1[tid];
#pragma unroll 8
        for (int k = 0; k < CC; k++) {
            float w = W1[k * NCLS + tid];
            g_W1f[k * NCLS + tid] = s_scale[k] * w;
            acc += s_shift[k] * w;
        }
        g_b1f[tid] = acc;
    }
}

// ---------------- classifier + log_softmax ----------------
__global__ void k_classify(float* __restrict__ out) {
    __shared__ float Ws[CC * NCLS];
    __shared__ float bs[NCLS];
    if (threadIdx.x < CC * NCLS) Ws[threadIdx.x] = g_W1f[threadIdx.x];
    if (threadIdx.x < NCLS) bs[threadIdx.x] = g_b1f[threadIdx.x];
    __syncthreads();
    int node = blockIdx.x * blockDim.x + threadIdx.x;
    if (node >= NN) return;
    float l0 = bs[0], l1 = bs[1], l2 = bs[2], l3 = bs[3];
#pragma unroll 8
    for (int k = 0; k < CC; k++) {
        float h = g_h[node * CC + k];
        l0 += h * Ws[k * 4 + 0];
        l1 += h * Ws[k * 4 + 1];
        l2 += h * Ws[k * 4 + 2];
        l3 += h * Ws[k * 4 + 3];
    }
    float m = fmaxf(fmaxf(l0, l1), fmaxf(l2, l3));
    float s = __expf(l0 - m) + __expf(l1 - m) + __expf(l2 - m) + __expf(l3 - m);
    float ls = m + __logf(s);
    float4 o;
    o.x = l0 - ls; o.y = l1 - ls; o.z = l2 - ls; o.w = l3 - ls;
    *(float4*)(out + node * 4) = o;
}

// ---------------- launcher ----------------
extern "C" void kernel_launch(void* const* d_in, const int* in_sizes, int n_in,
                              void* d_out, int out_size) {
    const float* x     = (const float*)d_in[0];
    const int*   ei    = (const int*)d_in[1];
    const float* Wl1   = (const float*)d_in[2];
    const float* bl1   = (const float*)d_in[3];
    const float* Wr1   = (const float*)d_in[4];
    const float* br1   = (const float*)d_in[5];
    const float* att1  = (const float*)d_in[6];
    const float* bias1 = (const float*)d_in[7];
    const float* gng1  = (const float*)d_in[8];
    const float* gnb1  = (const float*)d_in[9];
    const float* gna1  = (const float*)d_in[10];
    const float* Wl2   = (const float*)d_in[11];
    const float* bl2   = (const float*)d_in[12];
    const float* Wr2   = (const float*)d_in[13];
    const float* br2   = (const float*)d_in[14];
    const float* att2  = (const float*)d_in[15];
    const float* bias2 = (const float*)d_in[16];
    const float* gng2  = (const float*)d_in[17];
    const float* gnb2  = (const float*)d_in[18];
    const float* gna2  = (const float*)d_in[19];
    const float* W1    = (const float*)d_in[20];
    const float* b1    = (const float*)d_in[21];
    float* out = (float*)d_out;

    float *p_xr, *p_h, *p_blf, *p_brf;
    __half *p_xlh;
    __nv_bfloat16 *p_Ah, *p_Al, *p_Blh, *p_Bll, *p_Brh, *p_Brl;
    cudaGetSymbolAddress((void**)&p_xlh, g_xlh);
    cudaGetSymbolAddress((void**)&p_xr,  g_xr);
    cudaGetSymbolAddress((void**)&p_h,   g_h);
    cudaGetSymbolAddress((void**)&p_blf, g_blf);
    cudaGetSymbolAddress((void**)&p_brf, g_brf);
    cudaGetSymbolAddress((void**)&p_Ah,  g_Ah);
    cudaGetSymbolAddress((void**)&p_Al,  g_Al);
    cudaGetSymbolAddress((void**)&p_Blh, g_Blh);
    cudaGetSymbolAddress((void**)&p_Bll, g_Bll);
    cudaGetSymbolAddress((void**)&p_Brh, g_Brh);
    cudaGetSymbolAddress((void**)&p_Brl, g_Brl);

    cudaFuncSetAttribute(k_mma_gemm<128>, cudaFuncAttributeMaxDynamicSharedMemorySize, SMEM_TOT);
    cudaFuncSetAttribute(k_mma_gemm<64>,  cudaFuncAttributeMaxDynamicSharedMemorySize, SMEM_TOT);

    const int TB = 256;
    int gN   = (NN + TB - 1) / TB;
    int gC4  = (EE / 4 + TB - 1) / TB;
    int gS4  = (EE / 4 + (NN + 3) / 4 + TB - 1) / TB;
    int gNw  = (NN * 32 + TB - 1) / TB;
    int gCX  = (PADN * 32 + TB - 1) / TB;
    int gCW  = (2 * HC * HC + TB - 1) / TB;
    dim3 gG(GEMM_CTAS, 2);

    k_zero_deg<<<gN, TB>>>();                                          // 0
    k_conv_x<<<gCX, TB>>>(x);                                          // 1
    k_conv_w1<<<gCW, TB>>>(Wl1, Wr1);                                  // 2
    k_mma_gemm<128><<<gG, 256, SMEM_TOT>>>(                            // 3 (profiled)
        p_Ah, p_Al, p_Blh, p_Bll, p_Brh, p_Brl, bl1, br1, p_xlh, p_xr);
    k_count<<<gC4, TB>>>(ei);                                          // 4
    k_scan_chained<<<SCAN_NB, SCAN_B>>>();                             // 5
    k_scatter<<<gS4, TB>>>(ei);                                        // 6

    // ---- layer 1 aggregation ----
    k_attn_agg<<<gNw, TB>>>(p_xlh, p_xr, att1, bias1);                 // 7
    k_finalize_fold2<<<1, 256>>>(gng1, gnb1, gna1, Wl2, bl2, Wr2, br2);

    // ---- layer 2 ----
    k_mma_gemm<64><<<gG, 256, SMEM_TOT>>>(
        p_Ah, p_Al, p_Blh, p_Bll, p_Brh, p_Brl, p_blf, p_brf, p_xlh, p_xr);
    k_attn_agg<<<gNw, TB>>>(p_xlh, p_xr, att2, bias2);
    k_finalize_fold_final<<<1, 64>>>(gng2, gnb2, gna2, W1, b1);

    k_classify<<<gN, TB>>>(out);
}

// round 15
// speedup vs baseline: 1.4398x; 1.4398x over previous
#include <cuda_runtime.h>
#include <cuda_bf16.h>
#include <cuda_fp16.h>
#include <math.h>
#include <stdint.h>

#define NN 50000
#define EE 800000
#define ET 850000
#define CC 64
#define HC 128
#define NCLS 4
#define EPS_GN 1e-5f
#define SCAN_B 1024
#define SCAN_NB ((NN + SCAN_B - 1) / SCAN_B)
#define PADN 50048            /* 391 * 128 */
#define GEMM_CTAS (PADN / 128)
#define ASTR 40               /* A smem row stride (elems): conflict-free ldmatrix */
#define WSTR 136              /* W smem row stride (elems): conflict-free ldmatrix */

#define ATILE (128 * ASTR * 2)     /* bytes per A split tile: 10240 */
#define WTILE (32 * WSTR * 2)      /* bytes per W split tile: 8704 */
#define ABUF  (ATILE * 2)          /* hi+lo */
#define WBUF  (WTILE * 2)
#define SMEM_W_OFF (ABUF * 2)
#define SMEM_TOT (ABUF * 2 + WBUF * 2)   /* 75776 */

// ---------------- mma / cp.async helpers (base-target PTX: sm_80+) ----------------
__device__ __forceinline__ uint32_t smem_u32(const void* p) {
    uint32_t a;
    asm("{ .reg .u64 t; cvta.to.shared.u64 t, %1; cvt.u32.u64 %0, t; }" : "=r"(a) : "l"(p));
    return a;
}
__device__ __forceinline__ void ldsm_x4(uint32_t& r0, uint32_t& r1, uint32_t& r2, uint32_t& r3, uint32_t addr) {
    asm volatile("ldmatrix.sync.aligned.m8n8.x4.shared.b16 {%0,%1,%2,%3}, [%4];"
                 : "=r"(r0), "=r"(r1), "=r"(r2), "=r"(r3) : "r"(addr));
}
__device__ __forceinline__ void ldsm_x4_t(uint32_t& r0, uint32_t& r1, uint32_t& r2, uint32_t& r3, uint32_t addr) {
    asm volatile("ldmatrix.sync.aligned.m8n8.x4.trans.shared.b16 {%0,%1,%2,%3}, [%4];"
                 : "=r"(r0), "=r"(r1), "=r"(r2), "=r"(r3) : "r"(addr));
}
__device__ __forceinline__ void mma_bf16(float* c, const uint32_t* a, const uint32_t* b) {
    asm volatile("mma.sync.aligned.m16n8k16.row.col.f32.bf16.bf16.f32 "
                 "{%0,%1,%2,%3}, {%4,%5,%6,%7}, {%8,%9}, {%0,%1,%2,%3};"
                 : "+f"(c[0]), "+f"(c[1]), "+f"(c[2]), "+f"(c[3])
                 : "r"(a[0]), "r"(a[1]), "r"(a[2]), "r"(a[3]), "r"(b[0]), "r"(b[1]));
}
__device__ __forceinline__ void cp16(uint32_t dst, const void* src) {
    asm volatile("cp.async.cg.shared.global [%0], [%1], 16;" :: "r"(dst), "l"(src));
}
#define CP_COMMIT() asm volatile("cp.async.commit_group;" ::: "memory")
#define CP_WAIT1()  asm volatile("cp.async.wait_group 1;" ::: "memory")
#define CP_WAIT0()  asm volatile("cp.async.wait_group 0;" ::: "memory")

// ---------------- scratch ----------------
__device__ __align__(16) __half g_xlh[NN * HC];   /* fp16 source-transform (attention gather payload) */
__device__ __align__(16) float g_xr[NN * HC];
__device__ __align__(16) float g_h[NN * CC];
__device__ __align__(16) __nv_bfloat16 g_Ah[PADN * HC];
__device__ __align__(16) __nv_bfloat16 g_Al[PADN * HC];
__device__ __align__(16) __nv_bfloat16 g_Blh[HC * HC], g_Bll[HC * HC];
__device__ __align__(16) __nv_bfloat16 g_Brh[HC * HC], g_Brl[HC * HC];
__device__ __align__(16) int   g_deg[NN];
__device__ int   g_rowptr[NN + 1];
__device__ int   g_cursor[NN];
__device__ int   g_csrc[ET];
__device__ int   g_scanval[64];
__device__ __align__(16) int g_scanflag[64];
__device__ float g_sum[CC], g_sumsq[CC];
__device__ __align__(16) float g_blf[HC], g_brf[HC];
__device__ float g_W1f[CC * NCLS], g_b1f[NCLS];

// ---------------- CSR build ----------------
__global__ void k_zero_deg() {
    int i = blockIdx.x * blockDim.x + threadIdx.x;
    int4 z = make_int4(0, 0, 0, 0);
    if (i < NN / 4) ((int4*)g_deg)[i] = z;
    if (i < 16)     ((int4*)g_scanflag)[i] = z;
}

__global__ void k_count(const int* __restrict__ ei) {
    int t = blockIdx.x * blockDim.x + threadIdx.x;
    if (t >= EE / 4) return;
    int4 d = ((const int4*)(ei + EE))[t];
    atomicAdd(&g_deg[d.x], 1);
    atomicAdd(&g_deg[d.y], 1);
    atomicAdd(&g_deg[d.z], 1);
    atomicAdd(&g_deg[d.w], 1);
}

__global__ void k_scan_chained() {
    __shared__ int sh[SCAN_B];
    __shared__ int s_prefix;
    int b = blockIdx.x, tid = threadIdx.x;
    int i = b * SCAN_B + tid;
    int v = (i < NN) ? (g_deg[i] + 1) : 0;
    sh[tid] = v;
    __syncthreads();
#pragma unroll
    for (int off = 1; off < SCAN_B; off <<= 1) {
        int t = (tid >= off) ? sh[tid - off] : 0;
        __syncthreads();
        sh[tid] += t;
        __syncthreads();
    }
    if (tid == 0) {
        int prefix = 0;
        if (b > 0) {
            while (atomicAdd(&g_scanflag[b - 1], 0) == 0) { }
            prefix = g_scanval[b - 1];
        }
        s_prefix = prefix;
        g_scanval[b] = prefix + sh[SCAN_B - 1];
        __threadfence();
        atomicExch(&g_scanflag[b], 1);
        if (b == SCAN_NB - 1) g_rowptr[NN] = prefix + sh[SCAN_B - 1];
    }
    __syncthreads();
    if (i < NN) {
        int excl = s_prefix + sh[tid] - v;
        g_rowptr[i] = excl;
        g_cursor[i] = excl;
    }
    if (b == 0 && tid < CC) { g_sum[tid] = 0.0f; g_sumsq[tid] = 0.0f; }
}

__global__ void k_scatter(const int* __restrict__ ei) {
    int t = blockIdx.x * blockDim.x + threadIdx.x;
    if (t < EE / 4) {
        int4 s = ((const int4*)ei)[t];
        int4 d = ((const int4*)(ei + EE))[t];
        int p;
        p = atomicAdd(&g_cursor[d.x], 1); g_csrc[p] = s.x;
        p = atomicAdd(&g_cursor[d.y], 1); g_csrc[p] = s.y;
        p = atomicAdd(&g_cursor[d.z], 1); g_csrc[p] = s.z;
        p = atomicAdd(&g_cursor[d.w], 1); g_csrc[p] = s.w;
    } else {
        int base = (t - EE / 4) * 4;
#pragma unroll
        for (int j = 0; j < 4; j++) {
            int i = base + j;
            if (i < NN) {
                int p = atomicAdd(&g_cursor[i], 1);
                g_csrc[p] = i;
            }
        }
    }
}

// ---------------- fp32 -> (hi, lo) bf16 split ----------------
__device__ __forceinline__ void split_bf16(float x, __nv_bfloat16& hi, __nv_bfloat16& lo) {
    hi = __float2bfloat16(x);
    lo = __float2bfloat16(x - __bfloat162float(hi));
}

__global__ void k_conv_x(const float* __restrict__ x) {
    int t = blockIdx.x * blockDim.x + threadIdx.x;
    if (t >= PADN * 32) return;
    int row = t >> 5;
    int c4 = (t & 31) * 4;
    float4 v = make_float4(0.f, 0.f, 0.f, 0.f);
    if (row < NN) v = *(const float4*)(x + row * HC + c4);
    __nv_bfloat16 h0, h1, h2, h3, l0, l1, l2, l3;
    split_bf16(v.x, h0, l0); split_bf16(v.y, h1, l1);
    split_bf16(v.z, h2, l2); split_bf16(v.w, h3, l3);
    __nv_bfloat162* ph = (__nv_bfloat162*)(g_Ah + row * HC + c4);
    __nv_bfloat162* pl = (__nv_bfloat162*)(g_Al + row * HC + c4);
    ph[0] = __nv_bfloat162(h0, h1); ph[1] = __nv_bfloat162(h2, h3);
    pl[0] = __nv_bfloat162(l0, l1); pl[1] = __nv_bfloat162(l2, l3);
}

__global__ void k_conv_w1(const float* __restrict__ Wl, const float* __restrict__ Wr) {
    int t = blockIdx.x * blockDim.x + threadIdx.x;
    if (t >= 2 * HC * HC) return;
    int which = t >> 14;
    int r = t & 16383;
    const float* W = which ? Wr : Wl;
    __nv_bfloat16 *Bh = which ? g_Brh : g_Blh, *Bl = which ? g_Brl : g_Bll;
    __nv_bfloat16 hi, lo;
    split_bf16(W[r], hi, lo);
    Bh[r] = hi;
    Bl[r] = lo;
}

// ---------------- split-bf16 tensor-core GEMM, cp.async double-buffered ----------------
// blockIdx.y==0 -> xl path (fp16 output); ==1 -> xr path (fp32 output)
template<int K>
__global__ void __launch_bounds__(256, 2)
k_mma_gemm(const __nv_bfloat16* __restrict__ Ah, const __nv_bfloat16* __restrict__ Al,
           const __nv_bfloat16* __restrict__ Blh, const __nv_bfloat16* __restrict__ Bll,
           const __nv_bfloat16* __restrict__ Brh, const __nv_bfloat16* __restrict__ Brl,
           const float* __restrict__ bl, const float* __restrict__ br,
           __half* __restrict__ outl, float* __restrict__ outr) {
    extern __shared__ char smem[];
    uint32_t sbase = smem_u32(smem);
    const __nv_bfloat16* Bh = blockIdx.y ? Brh : Blh;
    const __nv_bfloat16* Bl = blockIdx.y ? Brl : Bll;
    const float* bias = blockIdx.y ? br : bl;

    int tid = threadIdx.x;
    int wid = tid >> 5, lane = tid & 31;
    int wr = wid & 3;
    int wc = wid >> 2;
    int row0 = blockIdx.x * 128;
    constexpr int T = K / 32;

    float acc[2][8][4];
#pragma unroll
    for (int m = 0; m < 2; m++)
#pragma unroll
        for (int n = 0; n < 8; n++)
#pragma unroll
            for (int q = 0; q < 4; q++) acc[m][n][q] = 0.0f;

#define LOAD_TILE(kt, buf) do {                                               \
        int k0_ = (kt) * 32;                                                  \
        uint32_t ab_ = sbase + (buf) * ABUF;                                  \
        uint32_t wb_ = sbase + SMEM_W_OFF + (buf) * WBUF;                     \
        _Pragma("unroll")                                                     \
        for (int i_ = 0; i_ < 2; i_++) {                                      \
            int id_ = tid + i_ * 256;                                         \
            int r_ = id_ >> 2, c8_ = (id_ & 3) * 8;                           \
            size_t go_ = (size_t)(row0 + r_) * K + k0_ + c8_;                 \
            cp16(ab_ + (r_ * ASTR + c8_) * 2, Ah + go_);                      \
            cp16(ab_ + ATILE + (r_ * ASTR + c8_) * 2, Al + go_);              \
        }                                                                     \
        _Pragma("unroll")                                                     \
        for (int i_ = 0; i_ < 2; i_++) {                                      \
            int id_ = tid + i_ * 256;                                         \
            int kk_ = id_ >> 4, n8_ = (id_ & 15) * 8;                         \
            int go_ = (k0_ + kk_) * 128 + n8_;                                \
            cp16(wb_ + (kk_ * WSTR + n8_) * 2, Bh + go_);                     \
            cp16(wb_ + WTILE + (kk_ * WSTR + n8_) * 2, Bl + go_);             \
        }                                                                     \
    } while (0)

    LOAD_TILE(0, 0);
    CP_COMMIT();

#pragma unroll
    for (int kt = 0; kt < T; kt++) {
        int buf = kt & 1;
        if (kt + 1 < T) {
            LOAD_TILE(kt + 1, (kt + 1) & 1);
            CP_COMMIT();
            CP_WAIT1();
        } else {
            CP_WAIT0();
        }
        __syncthreads();
        uint32_t aHB = sbase + buf * ABUF;
        uint32_t aLB = aHB + ATILE;
        uint32_t wHB = sbase + SMEM_W_OFF + buf * WBUF;
        uint32_t wLB = wHB + WTILE;
#pragma unroll
        for (int kk = 0; kk < 32; kk += 16) {
            uint32_t ah[2][4], al[2][4];
#pragma unroll
            for (int m = 0; m < 2; m++) {
                int arow = wr * 32 + m * 16 + (lane & 15);
                int acol = kk + (lane >> 4) * 8;
                uint32_t off = (uint32_t)(arow * ASTR + acol) * 2;
                ldsm_x4(ah[m][0], ah[m][1], ah[m][2], ah[m][3], aHB + off);
                ldsm_x4(al[m][0], al[m][1], al[m][2], al[m][3], aLB + off);
            }
#pragma unroll
            for (int np = 0; np < 4; np++) {
                int krow = kk + (lane & 7) + ((lane >> 3) & 1) * 8;
                int ncol = wc * 64 + np * 16 + (lane >> 4) * 8;
                uint32_t off = (uint32_t)(krow * WSTR + ncol) * 2;
                uint32_t bh[4], blo[4];
                ldsm_x4_t(bh[0], bh[1], bh[2], bh[3], wHB + off);
                ldsm_x4_t(blo[0], blo[1], blo[2], blo[3], wLB + off);
#pragma unroll
                for (int m = 0; m < 2; m++) {
#pragma unroll
                    for (int nn = 0; nn < 2; nn++) {
                        float* c = acc[m][np * 2 + nn];
                        mma_bf16(c, ah[m], &bh[nn * 2]);
                        mma_bf16(c, ah[m], &blo[nn * 2]);
                        mma_bf16(c, al[m], &bh[nn * 2]);
                    }
                }
            }
        }
        __syncthreads();
    }
#undef LOAD_TILE

    // epilogue: block-uniform branch hoisted outside the store loops
    int rb = row0 + wr * 32 + (lane >> 2);
    int cb = wc * 64 + (lane & 3) * 2;
    if (blockIdx.y) {          // xr path: fp32
#pragma unroll
        for (int m = 0; m < 2; m++) {
#pragma unroll
            for (int nt = 0; nt < 8; nt++) {
                int cc0 = cb + nt * 8;
                float b0 = __ldg(bias + cc0), b1 = __ldg(bias + cc0 + 1);
                int r1 = rb + m * 16;
                int r2 = r1 + 8;
                if (r1 < NN)
                    *(float2*)(outr + (size_t)r1 * HC + cc0) =
                        make_float2(acc[m][nt][0] + b0, acc[m][nt][1] + b1);
                if (r2 < NN)
                    *(float2*)(outr + (size_t)r2 * HC + cc0) =
                        make_float2(acc[m][nt][2] + b0, acc[m][nt][3] + b1);
            }
        }
    } else {                   // xl path: fp16
#pragma unroll
        for (int m = 0; m < 2; m++) {
#pragma unroll
            for (int nt = 0; nt < 8; nt++) {
                int cc0 = cb + nt * 8;
                float b0 = __ldg(bias + cc0), b1 = __ldg(bias + cc0 + 1);
                int r1 = rb + m * 16;
                int r2 = r1 + 8;
                if (r1 < NN)
                    *(__half2*)(outl + (size_t)r1 * HC + cc0) =
                        __floats2half2_rn(acc[m][nt][0] + b0, acc[m][nt][1] + b1);
                if (r2 < NN)
                    *(__half2*)(outl + (size_t)r2 * HC + cc0) =
                        __floats2half2_rn(acc[m][nt][2] + b0, acc[m][nt][3] + b1);
            }
        }
    }
}

// ---- fused attention + softmax (shift-invariant, no max pass) + aggregation ----
// + GraphNorm stats + bf16 split of h.  warp per node, 2-edge software pipeline.
// xl gathered in fp16 (half the L2 traffic); xr per-node in fp32.
__global__ void k_attn_agg(const __half* __restrict__ xl, const float* __restrict__ xr,
                           const float* __restrict__ att, const float* __restrict__ bias) {
    __shared__ float s_sum[CC], s_sq[CC];
    int tid = threadIdx.x;
    if (tid < CC) { s_sum[tid] = 0.0f; s_sq[tid] = 0.0f; }
    __syncthreads();

    int node = (blockIdx.x * blockDim.x + tid) >> 5;
    int lane = tid & 31;
    bool active = node < NN;
    int s0 = 0, s1 = 0;
    if (active) { s0 = g_rowptr[node]; s1 = g_rowptr[node + 1]; }
    float4 t4 = *(const float4*)(att + lane * 4);
    float4 xq = make_float4(0.f, 0.f, 0.f, 0.f);
    if (active) xq = *(const float4*)(xr + node * HC + lane * 4);

    float denom = 0.0f;
    float a0 = 0.0f, a1 = 0.0f, a2 = 0.0f, a3 = 0.0f;

#define GATHER(i, vv) do {                                                       \
        int sn_ = __ldg(&g_csrc[i]);                                             \
        uint2 raw_ = *(const uint2*)(xl + (size_t)sn_ * HC + lane * 4);          \
        float2 f01_ = __half22float2(*(__half2*)&raw_.x);                        \
        float2 f23_ = __half22float2(*(__half2*)&raw_.y);                        \
        vv = make_float4(f01_.x, f01_.y, f23_.x, f23_.y);                        \
    } while (0)

#define DOTP(vv, pp) do {                                   \
        float m_;                                            \
        pp = 0.0f;                                           \
        m_ = vv.x + xq.x; pp += fmaxf(m_, 0.2f * m_) * t4.x; \
        m_ = vv.y + xq.y; pp += fmaxf(m_, 0.2f * m_) * t4.y; \
        m_ = vv.z + xq.z; pp += fmaxf(m_, 0.2f * m_) * t4.z; \
        m_ = vv.w + xq.w; pp += fmaxf(m_, 0.2f * m_) * t4.w; \
    } while (0)

    int idx = s0;
    float4 v0 = make_float4(0.f, 0.f, 0.f, 0.f);
    float4 v1 = v0;
    if (idx < s1)     GATHER(idx, v0);
    if (idx + 1 < s1) GATHER(idx + 1, v1);
    for (; idx + 1 < s1; idx += 2) {
        float4 c0 = v0, c1 = v1;
        if (idx + 2 < s1) GATHER(idx + 2, v0);
        if (idx + 3 < s1) GATHER(idx + 3, v1);
        float pa, pb;
        DOTP(c0, pa);
        DOTP(c1, pb);
        pa += __shfl_xor_sync(0xffffffffu, pa, 8);
        pb += __shfl_xor_sync(0xffffffffu, pb, 8);
        pa += __shfl_xor_sync(0xffffffffu, pa, 4);
        pb += __shfl_xor_sync(0xffffffffu, pb, 4);
        pa += __shfl_xor_sync(0xffffffffu, pa, 2);
        pb += __shfl_xor_sync(0xffffffffu, pb, 2);
        pa += __shfl_xor_sync(0xffffffffu, pa, 1);
        pb += __shfl_xor_sync(0xffffffffu, pb, 1);
        float wa = __expf(pa), wb = __expf(pb);
        a0 += wa * c0.x + wb * c1.x;
        a1 += wa * c0.y + wb * c1.y;
        a2 += wa * c0.z + wb * c1.z;
        a3 += wa * c0.w + wb * c1.w;
        denom += wa + wb;
    }
    if (idx < s1) {                     // odd tail
        float p;
        DOTP(v0, p);
        p += __shfl_xor_sync(0xffffffffu, p, 8);
        p += __shfl_xor_sync(0xffffffffu, p, 4);
        p += __shfl_xor_sync(0xffffffffu, p, 2);
        p += __shfl_xor_sync(0xffffffffu, p, 1);
        float w = __expf(p);
        a0 += w * v0.x;
        a1 += w * v0.y;
        a2 += w * v0.z;
        a3 += w * v0.w;
        denom += w;
    }
#undef DOTP
#undef GATHER

    float inv = 1.0f / (denom + 1e-16f);
    a0 *= inv; a1 *= inv; a2 *= inv; a3 *= inv;
    a0 = 0.5f * (a0 + __shfl_down_sync(0xffffffffu, a0, 16));
    a1 = 0.5f * (a1 + __shfl_down_sync(0xffffffffu, a1, 16));
    a2 = 0.5f * (a2 + __shfl_down_sync(0xffffffffu, a2, 16));
    a3 = 0.5f * (a3 + __shfl_down_sync(0xffffffffu, a3, 16));
    if (active && lane < 16) {
        float4 bb = *(const float4*)(bias + lane * 4);
        float4 o;
        o.x = a0 + bb.x; o.y = a1 + bb.y; o.z = a2 + bb.z; o.w = a3 + bb.w;
        *(float4*)(g_h + node * CC + lane * 4) = o;
        __nv_bfloat16 h0, h1, h2, h3, l0, l1, l2, l3;
        split_bf16(o.x, h0, l0); split_bf16(o.y, h1, l1);
        split_bf16(o.z, h2, l2); split_bf16(o.w, h3, l3);
        __nv_bfloat162* ph = (__nv_bfloat162*)(g_Ah + node * CC + lane * 4);
        __nv_bfloat162* pl = (__nv_bfloat162*)(g_Al + node * CC + lane * 4);
        ph[0] = __nv_bfloat162(h0, h1); ph[1] = __nv_bfloat162(h2, h3);
        pl[0] = __nv_bfloat162(l0, l1); pl[1] = __nv_bfloat162(l2, l3);
        int c4 = lane * 4;
        atomicAdd(&s_sum[c4 + 0], o.x); atomicAdd(&s_sq[c4 + 0], o.x * o.x);
        atomicAdd(&s_sum[c4 + 1], o.y); atomicAdd(&s_sq[c4 + 1], o.y * o.y);
        atomicAdd(&s_sum[c4 + 2], o.z); atomicAdd(&s_sq[c4 + 2], o.z * o.z);
        atomicAdd(&s_sum[c4 + 3], o.w); atomicAdd(&s_sq[c4 + 3], o.w * o.w);
    }
    __syncthreads();
    if (tid < CC) {
        atomicAdd(&g_sum[tid], s_sum[tid]);
        atomicAdd(&g_sumsq[tid], s_sq[tid]);
    }
}

// ---- GraphNorm finalize + fold into layer-2 weights (splits stay [k][n]) ----
__global__ void k_finalize_fold2(const float* __restrict__ gamma,
                                 const float* __restrict__ beta,
                                 const float* __restrict__ a,
                                 const float* __restrict__ Wl, const float* __restrict__ bl,
                                 const float* __restrict__ Wr, const float* __restrict__ br) {
    __shared__ float s_scale[CC], s_shift[CC];
    int tid = threadIdx.x;
    if (tid < CC) {
        float mean = g_sum[tid] * (1.0f / NN);
        float ex2  = g_sumsq[tid] * (1.0f / NN);
        float ac = a[tid];
        float var = ex2 - 2.0f * ac * mean * mean + ac * ac * mean * mean;
        float r = rsqrtf(var + EPS_GN);
        float sc = gamma[tid] * r;
        s_scale[tid] = sc;
        s_shift[tid] = beta[tid] - sc * ac * mean;
        g_sum[tid] = 0.0f;
        g_sumsq[tid] = 0.0f;
    }
    __syncthreads();
    int j = tid & 127;
    int which = tid >> 7;
    const float* W = which ? Wr : Wl;
    const float* b = which ? br : bl;
    __nv_bfloat16* Bh = which ? g_Brh : g_Blh;
    __nv_bfloat16* Bl = which ? g_Brl : g_Bll;
    float* bf = which ? g_brf : g_blf;
    float acc = b[j];
#pragma unroll 8
    for (int k = 0; k < CC; k++) {
        float w = W[k * 128 + j];
        float wf = s_scale[k] * w;
        __nv_bfloat16 hi, lo;
        split_bf16(wf, hi, lo);
        Bh[k * 128 + j] = hi;
        Bl[k * 128 + j] = lo;
        acc += s_shift[k] * w;
    }
    bf[j] = acc;
}

__global__ void k_finalize_fold_final(const float* __restrict__ gamma,
                                      const float* __restrict__ beta,
                                      const float* __restrict__ a,
                                      const float* __restrict__ W1, const float* __restrict__ b1) {
    __shared__ float s_scale[CC], s_shift[CC];
    int tid = threadIdx.x;
    if (tid < CC) {
        float mean = g_sum[tid] * (1.0f / NN);
        float ex2  = g_sumsq[tid] * (1.0f / NN);
        float ac = a[tid];
        float var = ex2 - 2.0f * ac * mean * mean + ac * ac * mean * mean;
        float r = rsqrtf(var + EPS_GN);
        float sc = gamma[tid] * r;
        s_scale[tid] = sc;
        s_shift[tid] = beta[tid] - sc * ac * mean;
    }
    __syncthreads();
    if (tid < NCLS) {
        float acc = b1[tid];
#pragma unroll 8
        for (int k = 0; k < CC; k++) {
            float w = W1[k * NCLS + tid];
            g_W1f[k * NCLS + tid] = s_scale[k] * w;
            acc += s_shift[k] * w;
        }
        g_b1f[tid] = acc;
    }
}

// ---------------- classifier + log_softmax ----------------
__global__ void k_classify(float* __restrict__ out) {
    __shared__ float Ws[CC * NCLS];
    __shared__ float bs[NCLS];
    if (threadIdx.x < CC * NCLS) Ws[threadIdx.x] = g_W1f[threadIdx.x];
    if (threadIdx.x < NCLS) bs[threadIdx.x] = g_b1f[threadIdx.x];
    __syncthreads();
    int node = blockIdx.x * blockDim.x + threadIdx.x;
    if (node >= NN) return;
    float l0 = bs[0], l1 = bs[1], l2 = bs[2], l3 = bs[3];
#pragma unroll 8
    for (int k = 0; k < CC; k++) {
        float h = g_h[node * CC + k];
        l0 += h * Ws[k * 4 + 0];
        l1 += h * Ws[k * 4 + 1];
        l2 += h * Ws[k * 4 + 2];
        l3 += h * Ws[k * 4 + 3];
    }
    float m = fmaxf(fmaxf(l0, l1), fmaxf(l2, l3));
    float s = __expf(l0 - m) + __expf(l1 - m) + __expf(l2 - m) + __expf(l3 - m);
    float ls = m + __logf(s);
    float4 o;
    o.x = l0 - ls; o.y = l1 - ls; o.z = l2 - ls; o.w = l3 - ls;
    *(float4*)(out + node * 4) = o;
}

// ---------------- launcher ----------------
extern "C" void kernel_launch(void* const* d_in, const int* in_sizes, int n_in,
                              void* d_out, int out_size) {
    const float* x     = (const float*)d_in[0];
    const int*   ei    = (const int*)d_in[1];
    const float* Wl1   = (const float*)d_in[2];
    const float* bl1   = (const float*)d_in[3];
    const float* Wr1   = (const float*)d_in[4];
    const float* br1   = (const float*)d_in[5];
    const float* att1  = (const float*)d_in[6];
    const float* bias1 = (const float*)d_in[7];
    const float* gng1  = (const float*)d_in[8];
    const float* gnb1  = (const float*)d_in[9];
    const float* gna1  = (const float*)d_in[10];
    const float* Wl2   = (const float*)d_in[11];
    const float* bl2   = (const float*)d_in[12];
    const float* Wr2   = (const float*)d_in[13];
    const float* br2   = (const float*)d_in[14];
    const float* att2  = (const float*)d_in[15];
    const float* bias2 = (const float*)d_in[16];
    const float* gng2  = (const float*)d_in[17];
    const float* gnb2  = (const float*)d_in[18];
    const float* gna2  = (const float*)d_in[19];
    const float* W1    = (const float*)d_in[20];
    const float* b1    = (const float*)d_in[21];
    float* out = (float*)d_out;

    float *p_xr, *p_h, *p_blf, *p_brf;
    __half *p_xlh;
    __nv_bfloat16 *p_Ah, *p_Al, *p_Blh, *p_Bll, *p_Brh, *p_Brl;
    cudaGetSymbolAddress((void**)&p_xlh, g_xlh);
    cudaGetSymbolAddress((void**)&p_xr,  g_xr);
    cudaGetSymbolAddress((void**)&p_h,   g_h);
    cudaGetSymbolAddress((void**)&p_blf, g_blf);
    cudaGetSymbolAddress((void**)&p_brf, g_brf);
    cudaGetSymbolAddress((void**)&p_Ah,  g_Ah);
    cudaGetSymbolAddress((void**)&p_Al,  g_Al);
    cudaGetSymbolAddress((void**)&p_Blh, g_Blh);
    cudaGetSymbolAddress((void**)&p_Bll, g_Bll);
    cudaGetSymbolAddress((void**)&p_Brh, g_Brh);
    cudaGetSymbolAddress((void**)&p_Brl, g_Brl);

    cudaFuncSetAttribute(k_mma_gemm<128>, cudaFuncAttributeMaxDynamicSharedMemorySize, SMEM_TOT);
    cudaFuncSetAttribute(k_mma_gemm<64>,  cudaFuncAttributeMaxDynamicSharedMemorySize, SMEM_TOT);

    const int TB = 256;
    int gN   = (NN + TB - 1) / TB;
    int gC4  = (EE / 4 + TB - 1) / TB;
    int gS4  = (EE / 4 + (NN + 3) / 4 + TB - 1) / TB;
    int gNw  = (NN * 32 + TB - 1) / TB;
    int gCX  = (PADN * 32 + TB - 1) / TB;
    int gCW  = (2 * HC * HC + TB - 1) / TB;
    dim3 gG(GEMM_CTAS, 2);

    k_zero_deg<<<gN, TB>>>();                                          // 0
    k_conv_x<<<gCX, TB>>>(x);                                          // 1
    k_conv_w1<<<gCW, TB>>>(Wl1, Wr1);                                  // 2
    k_mma_gemm<128><<<gG, 256, SMEM_TOT>>>(                            // 3 (profiled)
        p_Ah, p_Al, p_Blh, p_Bll, p_Brh, p_Brl, bl1, br1, p_xlh, p_xr);
    k_count<<<gC4, TB>>>(ei);                                          // 4
    k_scan_chained<<<SCAN_NB, SCAN_B>>>();                             // 5
    k_scatter<<<gS4, TB>>>(ei);                                        // 6

    // ---- layer 1 aggregation ----
    k_attn_agg<<<gNw, TB>>>(p_xlh, p_xr, att1, bias1);                 // 7
    k_finalize_fold2<<<1, 256>>>(gng1, gnb1, gna1, Wl2, bl2, Wr2, br2);

    // ---- layer 2 ----
    k_mma_gemm<64><<<gG, 256, SMEM_TOT>>>(
        p_Ah, p_Al, p_Blh, p_Bll, p_Brh, p_Brl, p_blf, p_brf, p_xlh, p_xr);
    k_attn_agg<<<gNw, TB>>>(p_xlh, p_xr, att2, bias2);
    k_finalize_fold_final<<<1, 64>>>(gng2, gnb2, gna2, W1, b1);

    k_classify<<<gN, TB>>>(out);
}

// round 16
// speedup vs baseline: 1.5125x; 1.0505x over previous
#include <cuda_runtime.h>
#include <cuda_bf16.h>
#include <cuda_fp16.h>
#include <math.h>
#include <stdint.h>

#define NN 50000
#define EE 800000
#define ET 850000
#define CC 64
#define HC 128
#define NCLS 4
#define EPS_GN 1e-5f
#define SCAN_B 1024
#define SCAN_NB ((NN + SCAN_B - 1) / SCAN_B)
#define PADN 50048            /* 391 * 128 */
#define GEMM_CTAS (PADN / 128)
#define ASTR 40               /* A smem row stride (elems): conflict-free ldmatrix */
#define WSTR 136              /* W smem row stride (elems): conflict-free ldmatrix */

#define ATILE (128 * ASTR * 2)     /* bytes per A split tile: 10240 */
#define WTILE (32 * WSTR * 2)      /* bytes per W split tile: 8704 */
#define ABUF  (ATILE * 2)          /* hi+lo */
#define WBUF  (WTILE * 2)
#define SMEM_W_OFF (ABUF * 2)
#define SMEM_TOT (ABUF * 2 + WBUF * 2)   /* 75776 */

// ---------------- mma / cp.async helpers (base-target PTX: sm_80+) ----------------
__device__ __forceinline__ uint32_t smem_u32(const void* p) {
    uint32_t a;
    asm("{ .reg .u64 t; cvta.to.shared.u64 t, %1; cvt.u32.u64 %0, t; }" : "=r"(a) : "l"(p));
    return a;
}
__device__ __forceinline__ void ldsm_x4(uint32_t& r0, uint32_t& r1, uint32_t& r2, uint32_t& r3, uint32_t addr) {
    asm volatile("ldmatrix.sync.aligned.m8n8.x4.shared.b16 {%0,%1,%2,%3}, [%4];"
                 : "=r"(r0), "=r"(r1), "=r"(r2), "=r"(r3) : "r"(addr));
}
__device__ __forceinline__ void ldsm_x4_t(uint32_t& r0, uint32_t& r1, uint32_t& r2, uint32_t& r3, uint32_t addr) {
    asm volatile("ldmatrix.sync.aligned.m8n8.x4.trans.shared.b16 {%0,%1,%2,%3}, [%4];"
                 : "=r"(r0), "=r"(r1), "=r"(r2), "=r"(r3) : "r"(addr));
}
__device__ __forceinline__ void mma_bf16(float* c, const uint32_t* a, const uint32_t* b) {
    asm volatile("mma.sync.aligned.m16n8k16.row.col.f32.bf16.bf16.f32 "
                 "{%0,%1,%2,%3}, {%4,%5,%6,%7}, {%8,%9}, {%0,%1,%2,%3};"
                 : "+f"(c[0]), "+f"(c[1]), "+f"(c[2]), "+f"(c[3])
                 : "r"(a[0]), "r"(a[1]), "r"(a[2]), "r"(a[3]), "r"(b[0]), "r"(b[1]));
}
__device__ __forceinline__ void cp16(uint32_t dst, const void* src) {
    asm volatile("cp.async.cg.shared.global [%0], [%1], 16;" :: "r"(dst), "l"(src));
}
#define CP_COMMIT() asm volatile("cp.async.commit_group;" ::: "memory")
#define CP_WAIT1()  asm volatile("cp.async.wait_group 1;" ::: "memory")
#define CP_WAIT0()  asm volatile("cp.async.wait_group 0;" ::: "memory")

// ---------------- scratch ----------------
__device__ __align__(16) __half g_xlh[NN * HC];   /* fp16 source-transform (attention gather payload) */
__device__ __align__(16) float g_xr[NN * HC];
__device__ __align__(16) float g_h[NN * CC];
__device__ __align__(16) __nv_bfloat16 g_Ah[PADN * HC];
__device__ __align__(16) __nv_bfloat16 g_Al[PADN * HC];
__device__ __align__(16) __nv_bfloat16 g_Blh[HC * HC], g_Bll[HC * HC];
__device__ __align__(16) __nv_bfloat16 g_Brh[HC * HC], g_Brl[HC * HC];
__device__ __align__(16) int   g_deg[NN];
__device__ int   g_rowptr[NN + 1];
__device__ int   g_cursor[NN];
__device__ int   g_csrc[ET + 8];   /* +8 zero pad: unconditional prefetch */
__device__ int   g_scanval[64];
__device__ __align__(16) int g_scanflag[64];
__device__ float g_sum[CC], g_sumsq[CC];
__device__ __align__(16) float g_blf[HC], g_brf[HC];
__device__ float g_W1f[CC * NCLS], g_b1f[NCLS];

// ---------------- CSR build ----------------
__global__ void k_zero_deg() {
    int i = blockIdx.x * blockDim.x + threadIdx.x;
    int4 z = make_int4(0, 0, 0, 0);
    if (i < NN / 4) ((int4*)g_deg)[i] = z;
    if (i < 16)     ((int4*)g_scanflag)[i] = z;
    if (i < 8)      g_csrc[ET + i] = 0;     /* prefetch pad */
}

__global__ void k_count(const int* __restrict__ ei) {
    int t = blockIdx.x * blockDim.x + threadIdx.x;
    if (t >= EE / 4) return;
    int4 d = ((const int4*)(ei + EE))[t];
    atomicAdd(&g_deg[d.x], 1);
    atomicAdd(&g_deg[d.y], 1);
    atomicAdd(&g_deg[d.z], 1);
    atomicAdd(&g_deg[d.w], 1);
}

__global__ void k_scan_chained() {
    __shared__ int sh[SCAN_B];
    __shared__ int s_prefix;
    int b = blockIdx.x, tid = threadIdx.x;
    int i = b * SCAN_B + tid;
    int v = (i < NN) ? (g_deg[i] + 1) : 0;
    sh[tid] = v;
    __syncthreads();
#pragma unroll
    for (int off = 1; off < SCAN_B; off <<= 1) {
        int t = (tid >= off) ? sh[tid - off] : 0;
        __syncthreads();
        sh[tid] += t;
        __syncthreads();
    }
    if (tid == 0) {
        int prefix = 0;
        if (b > 0) {
            while (atomicAdd(&g_scanflag[b - 1], 0) == 0) { }
            prefix = g_scanval[b - 1];
        }
        s_prefix = prefix;
        g_scanval[b] = prefix + sh[SCAN_B - 1];
        __threadfence();
        atomicExch(&g_scanflag[b], 1);
        if (b == SCAN_NB - 1) g_rowptr[NN] = prefix + sh[SCAN_B - 1];
    }
    __syncthreads();
    if (i < NN) {
        int excl = s_prefix + sh[tid] - v;
        g_rowptr[i] = excl;
        g_cursor[i] = excl;
    }
    if (b == 0 && tid < CC) { g_sum[tid] = 0.0f; g_sumsq[tid] = 0.0f; }
}

__global__ void k_scatter(const int* __restrict__ ei) {
    int t = blockIdx.x * blockDim.x + threadIdx.x;
    if (t < EE / 4) {
        int4 s = ((const int4*)ei)[t];
        int4 d = ((const int4*)(ei + EE))[t];
        int p;
        p = atomicAdd(&g_cursor[d.x], 1); g_csrc[p] = s.x;
        p = atomicAdd(&g_cursor[d.y], 1); g_csrc[p] = s.y;
        p = atomicAdd(&g_cursor[d.z], 1); g_csrc[p] = s.z;
        p = atomicAdd(&g_cursor[d.w], 1); g_csrc[p] = s.w;
    } else {
        int base = (t - EE / 4) * 4;
#pragma unroll
        for (int j = 0; j < 4; j++) {
            int i = base + j;
            if (i < NN) {
                int p = atomicAdd(&g_cursor[i], 1);
                g_csrc[p] = i;
            }
        }
    }
}

// ---------------- fp32 -> (hi, lo) bf16 split ----------------
__device__ __forceinline__ void split_bf16(float x, __nv_bfloat16& hi, __nv_bfloat16& lo) {
    hi = __float2bfloat16(x);
    lo = __float2bfloat16(x - __bfloat162float(hi));
}

__global__ void k_conv_x(const float* __restrict__ x) {
    int t = blockIdx.x * blockDim.x + threadIdx.x;
    if (t >= PADN * 32) return;
    int row = t >> 5;
    int c4 = (t & 31) * 4;
    float4 v = make_float4(0.f, 0.f, 0.f, 0.f);
    if (row < NN) v = *(const float4*)(x + row * HC + c4);
    __nv_bfloat16 h0, h1, h2, h3, l0, l1, l2, l3;
    split_bf16(v.x, h0, l0); split_bf16(v.y, h1, l1);
    split_bf16(v.z, h2, l2); split_bf16(v.w, h3, l3);
    __nv_bfloat162* ph = (__nv_bfloat162*)(g_Ah + row * HC + c4);
    __nv_bfloat162* pl = (__nv_bfloat162*)(g_Al + row * HC + c4);
    ph[0] = __nv_bfloat162(h0, h1); ph[1] = __nv_bfloat162(h2, h3);
    pl[0] = __nv_bfloat162(l0, l1); pl[1] = __nv_bfloat162(l2, l3);
}

__global__ void k_conv_w1(const float* __restrict__ Wl, const float* __restrict__ Wr) {
    int t = blockIdx.x * blockDim.x + threadIdx.x;
    if (t >= 2 * HC * HC) return;
    int which = t >> 14;
    int r = t & 16383;
    const float* W = which ? Wr : Wl;
    __nv_bfloat16 *Bh = which ? g_Brh : g_Blh, *Bl = which ? g_Brl : g_Bll;
    __nv_bfloat16 hi, lo;
    split_bf16(W[r], hi, lo);
    Bh[r] = hi;
    Bl[r] = lo;
}

// ---------------- split-bf16 tensor-core GEMM, cp.async double-buffered ----------------
// blockIdx.y==0 -> xl path (fp16 output); ==1 -> xr path (fp32 output)
template<int K>
__global__ void __launch_bounds__(256, 2)
k_mma_gemm(const __nv_bfloat16* __restrict__ Ah, const __nv_bfloat16* __restrict__ Al,
           const __nv_bfloat16* __restrict__ Blh, const __nv_bfloat16* __restrict__ Bll,
           const __nv_bfloat16* __restrict__ Brh, const __nv_bfloat16* __restrict__ Brl,
           const float* __restrict__ bl, const float* __restrict__ br,
           __half* __restrict__ outl, float* __restrict__ outr) {
    extern __shared__ char smem[];
    uint32_t sbase = smem_u32(smem);
    const __nv_bfloat16* Bh = blockIdx.y ? Brh : Blh;
    const __nv_bfloat16* Bl = blockIdx.y ? Brl : Bll;
    const float* bias = blockIdx.y ? br : bl;

    int tid = threadIdx.x;
    int wid = tid >> 5, lane = tid & 31;
    int wr = wid & 3;
    int wc = wid >> 2;
    int row0 = blockIdx.x * 128;
    constexpr int T = K / 32;

    float acc[2][8][4];
#pragma unroll
    for (int m = 0; m < 2; m++)
#pragma unroll
        for (int n = 0; n < 8; n++)
#pragma unroll
            for (int q = 0; q < 4; q++) acc[m][n][q] = 0.0f;

#define LOAD_TILE(kt, buf) do {                                               \
        int k0_ = (kt) * 32;                                                  \
        uint32_t ab_ = sbase + (buf) * ABUF;                                  \
        uint32_t wb_ = sbase + SMEM_W_OFF + (buf) * WBUF;                     \
        _Pragma("unroll")                                                     \
        for (int i_ = 0; i_ < 2; i_++) {                                      \
            int id_ = tid + i_ * 256;                                         \
            int r_ = id_ >> 2, c8_ = (id_ & 3) * 8;                           \
            size_t go_ = (size_t)(row0 + r_) * K + k0_ + c8_;                 \
            cp16(ab_ + (r_ * ASTR + c8_) * 2, Ah + go_);                      \
            cp16(ab_ + ATILE + (r_ * ASTR + c8_) * 2, Al + go_);              \
        }                                                                     \
        _Pragma("unroll")                                                     \
        for (int i_ = 0; i_ < 2; i_++) {                                      \
            int id_ = tid + i_ * 256;                                         \
            int kk_ = id_ >> 4, n8_ = (id_ & 15) * 8;                         \
            int go_ = (k0_ + kk_) * 128 + n8_;                                \
            cp16(wb_ + (kk_ * WSTR + n8_) * 2, Bh + go_);                     \
            cp16(wb_ + WTILE + (kk_ * WSTR + n8_) * 2, Bl + go_);             \
        }                                                                     \
    } while (0)

    LOAD_TILE(0, 0);
    CP_COMMIT();

#pragma unroll
    for (int kt = 0; kt < T; kt++) {
        int buf = kt & 1;
        if (kt + 1 < T) {
            LOAD_TILE(kt + 1, (kt + 1) & 1);
            CP_COMMIT();
            CP_WAIT1();
        } else {
            CP_WAIT0();
        }
        __syncthreads();
        uint32_t aHB = sbase + buf * ABUF;
        uint32_t aLB = aHB + ATILE;
        uint32_t wHB = sbase + SMEM_W_OFF + buf * WBUF;
        uint32_t wLB = wHB + WTILE;
#pragma unroll
        for (int kk = 0; kk < 32; kk += 16) {
            uint32_t ah[2][4], al[2][4];
#pragma unroll
            for (int m = 0; m < 2; m++) {
                int arow = wr * 32 + m * 16 + (lane & 15);
                int acol = kk + (lane >> 4) * 8;
                uint32_t off = (uint32_t)(arow * ASTR + acol) * 2;
                ldsm_x4(ah[m][0], ah[m][1], ah[m][2], ah[m][3], aHB + off);
                ldsm_x4(al[m][0], al[m][1], al[m][2], al[m][3], aLB + off);
            }
#pragma unroll
            for (int np = 0; np < 4; np++) {
                int krow = kk + (lane & 7) + ((lane >> 3) & 1) * 8;
                int ncol = wc * 64 + np * 16 + (lane >> 4) * 8;
                uint32_t off = (uint32_t)(krow * WSTR + ncol) * 2;
                uint32_t bh[4], blo[4];
                ldsm_x4_t(bh[0], bh[1], bh[2], bh[3], wHB + off);
                ldsm_x4_t(blo[0], blo[1], blo[2], blo[3], wLB + off);
#pragma unroll
                for (int m = 0; m < 2; m++) {
#pragma unroll
                    for (int nn = 0; nn < 2; nn++) {
                        float* c = acc[m][np * 2 + nn];
                        mma_bf16(c, ah[m], &bh[nn * 2]);
                        mma_bf16(c, ah[m], &blo[nn * 2]);
                        mma_bf16(c, al[m], &bh[nn * 2]);
                    }
                }
            }
        }
        __syncthreads();
    }
#undef LOAD_TILE

    // epilogue: block-uniform branch hoisted outside the store loops
    int rb = row0 + wr * 32 + (lane >> 2);
    int cb = wc * 64 + (lane & 3) * 2;
    if (blockIdx.y) {          // xr path: fp32
#pragma unroll
        for (int m = 0; m < 2; m++) {
#pragma unroll
            for (int nt = 0; nt < 8; nt++) {
                int cc0 = cb + nt * 8;
                float b0 = __ldg(bias + cc0), b1 = __ldg(bias + cc0 + 1);
                int r1 = rb + m * 16;
                int r2 = r1 + 8;
                if (r1 < NN)
                    *(float2*)(outr + (size_t)r1 * HC + cc0) =
                        make_float2(acc[m][nt][0] + b0, acc[m][nt][1] + b1);
                if (r2 < NN)
                    *(float2*)(outr + (size_t)r2 * HC + cc0) =
                        make_float2(acc[m][nt][2] + b0, acc[m][nt][3] + b1);
            }
        }
    } else {                   // xl path: fp16
#pragma unroll
        for (int m = 0; m < 2; m++) {
#pragma unroll
            for (int nt = 0; nt < 8; nt++) {
                int cc0 = cb + nt * 8;
                float b0 = __ldg(bias + cc0), b1 = __ldg(bias + cc0 + 1);
                int r1 = rb + m * 16;
                int r2 = r1 + 8;
                if (r1 < NN)
                    *(__half2*)(outl + (size_t)r1 * HC + cc0) =
                        __floats2half2_rn(acc[m][nt][0] + b0, acc[m][nt][1] + b1);
                if (r2 < NN)
                    *(__half2*)(outl + (size_t)r2 * HC + cc0) =
                        __floats2half2_rn(acc[m][nt][2] + b0, acc[m][nt][3] + b1);
            }
        }
    }
}

// ---- fused attention + softmax (shift-invariant, no max pass) + aggregation ----
// + GraphNorm stats + bf16 split of h.  warp per node, 4-edge raw-fp16 prefetch queue.
__global__ void k_attn_agg(const __half* __restrict__ xl, const float* __restrict__ xr,
                           const float* __restrict__ att, const float* __restrict__ bias) {
    __shared__ float s_sum[CC], s_sq[CC];
    int tid = threadIdx.x;
    if (tid < CC) { s_sum[tid] = 0.0f; s_sq[tid] = 0.0f; }
    __syncthreads();

    int node = (blockIdx.x * blockDim.x + tid) >> 5;
    int lane = tid & 31;
    bool active = node < NN;
    int s0 = 0, s1 = 0;
    if (active) { s0 = g_rowptr[node]; s1 = g_rowptr[node + 1]; }
    float4 t4 = *(const float4*)(att + lane * 4);
    float4 xq = make_float4(0.f, 0.f, 0.f, 0.f);
    if (active) xq = *(const float4*)(xr + node * HC + lane * 4);

    float denom = 0.0f;
    float a0 = 0.0f, a1 = 0.0f, a2 = 0.0f, a3 = 0.0f;

    // raw fp16 gather (2 regs/edge); csrc padded by 8 zeros -> no guards needed
#define RAWLD(i, rr) do {                                                        \
        int sn_ = __ldg(&g_csrc[i]);                                             \
        rr = *(const uint2*)(xl + (size_t)sn_ * HC + lane * 4);                  \
    } while (0)

#define CVT4(rr, vv) do {                                                        \
        float2 f01_ = __half22float2(*(__half2*)&rr.x);                          \
        float2 f23_ = __half22float2(*(__half2*)&rr.y);                          \
        vv = make_float4(f01_.x, f01_.y, f23_.x, f23_.y);                        \
    } while (0)

#define DOTP(vv, pp) do {                                   \
        float m_;                                            \
        pp = 0.0f;                                           \
        m_ = vv.x + xq.x; pp += fmaxf(m_, 0.2f * m_) * t4.x; \
        m_ = vv.y + xq.y; pp += fmaxf(m_, 0.2f * m_) * t4.y; \
        m_ = vv.z + xq.z; pp += fmaxf(m_, 0.2f * m_) * t4.z; \
        m_ = vv.w + xq.w; pp += fmaxf(m_, 0.2f * m_) * t4.w; \
    } while (0)

    int idx = s0;
    uint2 r0, r1, r2, r3;
    RAWLD(idx, r0); RAWLD(idx + 1, r1);
    RAWLD(idx + 2, r2); RAWLD(idx + 3, r3);
    for (; idx + 1 < s1; idx += 2) {
        float4 c0, c1;
        CVT4(r0, c0); CVT4(r1, c1);
        r0 = r2; r1 = r3;
        RAWLD(idx + 4, r2); RAWLD(idx + 5, r3);   // 2-iteration prefetch distance
        float pa, pb;
        DOTP(c0, pa);
        DOTP(c1, pb);
        pa += __shfl_xor_sync(0xffffffffu, pa, 8);
        pb += __shfl_xor_sync(0xffffffffu, pb, 8);
        pa += __shfl_xor_sync(0xffffffffu, pa, 4);
        pb += __shfl_xor_sync(0xffffffffu, pb, 4);
        pa += __shfl_xor_sync(0xffffffffu, pa, 2);
        pb += __shfl_xor_sync(0xffffffffu, pb, 2);
        pa += __shfl_xor_sync(0xffffffffu, pa, 1);
        pb += __shfl_xor_sync(0xffffffffu, pb, 1);
        float wa = __expf(pa), wb = __expf(pb);
        a0 += wa * c0.x + wb * c1.x;
        a1 += wa * c0.y + wb * c1.y;
        a2 += wa * c0.z + wb * c1.z;
        a3 += wa * c0.w + wb * c1.w;
        denom += wa + wb;
    }
    if (idx < s1) {                     // odd tail (edge idx is in r0)
        float4 v;
        CVT4(r0, v);
        float p;
        DOTP(v, p);
        p += __shfl_xor_sync(0xffffffffu, p, 8);
        p += __shfl_xor_sync(0xffffffffu, p, 4);
        p += __shfl_xor_sync(0xffffffffu, p, 2);
        p += __shfl_xor_sync(0xffffffffu, p, 1);
        float w = __expf(p);
        a0 += w * v.x;
        a1 += w * v.y;
        a2 += w * v.z;
        a3 += w * v.w;
        denom += w;
    }
#undef DOTP
#undef CVT4
#undef RAWLD

    float inv = 1.0f / (denom + 1e-16f);
    a0 *= inv; a1 *= inv; a2 *= inv; a3 *= inv;
    a0 = 0.5f * (a0 + __shfl_down_sync(0xffffffffu, a0, 16));
    a1 = 0.5f * (a1 + __shfl_down_sync(0xffffffffu, a1, 16));
    a2 = 0.5f * (a2 + __shfl_down_sync(0xffffffffu, a2, 16));
    a3 = 0.5f * (a3 + __shfl_down_sync(0xffffffffu, a3, 16));
    if (active && lane < 16) {
        float4 bb = *(const float4*)(bias + lane * 4);
        float4 o;
        o.x = a0 + bb.x; o.y = a1 + bb.y; o.z = a2 + bb.z; o.w = a3 + bb.w;
        *(float4*)(g_h + node * CC + lane * 4) = o;
        __nv_bfloat16 h0, h1, h2, h3, l0, l1, l2, l3;
        split_bf16(o.x, h0, l0); split_bf16(o.y, h1, l1);
        split_bf16(o.z, h2, l2); split_bf16(o.w, h3, l3);
        __nv_bfloat162* ph = (__nv_bfloat162*)(g_Ah + node * CC + lane * 4);
        __nv_bfloat162* pl = (__nv_bfloat162*)(g_Al + node * CC + lane * 4);
        ph[0] = __nv_bfloat162(h0, h1); ph[1] = __nv_bfloat162(h2, h3);
        pl[0] = __nv_bfloat162(l0, l1); pl[1] = __nv_bfloat162(l2, l3);
        int c4 = lane * 4;
        atomicAdd(&s_sum[c4 + 0], o.x); atomicAdd(&s_sq[c4 + 0], o.x * o.x);
        atomicAdd(&s_sum[c4 + 1], o.y); atomicAdd(&s_sq[c4 + 1], o.y * o.y);
        atomicAdd(&s_sum[c4 + 2], o.z); atomicAdd(&s_sq[c4 + 2], o.z * o.z);
        atomicAdd(&s_sum[c4 + 3], o.w); atomicAdd(&s_sq[c4 + 3], o.w * o.w);
    }
    __syncthreads();
    if (tid < CC) {
        atomicAdd(&g_sum[tid], s_sum[tid]);
        atomicAdd(&g_sumsq[tid], s_sq[tid]);
    }
}

// ---- GraphNorm finalize + fold into layer-2 weights (splits stay [k][n]) ----
__global__ void k_finalize_fold2(const float* __restrict__ gamma,
                                 const float* __restrict__ beta,
                                 const float* __restrict__ a,
                                 const float* __restrict__ Wl, const float* __restrict__ bl,
                                 const float* __restrict__ Wr, const float* __restrict__ br) {
    __shared__ float s_scale[CC], s_shift[CC];
    int tid = threadIdx.x;
    if (tid < CC) {
        float mean = g_sum[tid] * (1.0f / NN);
        float ex2  = g_sumsq[tid] * (1.0f / NN);
        float ac = a[tid];
        float var = ex2 - 2.0f * ac * mean * mean + ac * ac * mean * mean;
        float r = rsqrtf(var + EPS_GN);
        float sc = gamma[tid] * r;
        s_scale[tid] = sc;
        s_shift[tid] = beta[tid] - sc * ac * mean;
        g_sum[tid] = 0.0f;
        g_sumsq[tid] = 0.0f;
    }
    __syncthreads();
    int j = tid & 127;
    int which = tid >> 7;
    const float* W = which ? Wr : Wl;
    const float* b = which ? br : bl;
    __nv_bfloat16* Bh = which ? g_Brh : g_Blh;
    __nv_bfloat16* Bl = which ? g_Brl : g_Bll;
    float* bf = which ? g_brf : g_blf;
    float acc = b[j];
#pragma unroll 8
    for (int k = 0; k < CC; k++) {
        float w = W[k * 128 + j];
        float wf = s_scale[k] * w;
        __nv_bfloat16 hi, lo;
        split_bf16(wf, hi, lo);
        Bh[k * 128 + j] = hi;
        Bl[k * 128 + j] = lo;
        acc += s_shift[k] * w;
    }
    bf[j] = acc;
}

__global__ void k_finalize_fold_final(const float* __restrict__ gamma,
                                      const float* __restrict__ beta,
                                      const float* __restrict__ a,
                                      const float* __restrict__ W1, const float* __restrict__ b1) {
    __shared__ float s_scale[CC], s_shift[CC];
    int tid = threadIdx.x;
    if (tid < CC) {
        float mean = g_sum[tid] * (1.0f / NN);
        float ex2  = g_sumsq[tid] * (1.0f / NN);
        float ac = a[tid];
        float var = ex2 - 2.0f * ac * mean * mean + ac * ac * mean * mean;
        float r = rsqrtf(var + EPS_GN);
        float sc = gamma[tid] * r;
        s_scale[tid] = sc;
        s_shift[tid] = beta[tid] - sc * ac * mean;
    }
    __syncthreads();
    if (tid < NCLS) {
        float acc = b1[tid];
#pragma unroll 8
        for (int k = 0; k < CC; k++) {
            float w = W1[k * NCLS + tid];
            g_W1f[k * NCLS + tid] = s_scale[k] * w;
            acc += s_shift[k] * w;
        }
        g_b1f[tid] = acc;
    }
}

// ---------------- classifier + log_softmax ----------------
__global__ void k_classify(float* __restrict__ out) {
    __shared__ float Ws[CC * NCLS];
    __shared__ float bs[NCLS];
    if (threadIdx.x < CC * NCLS) Ws[threadIdx.x] = g_W1f[threadIdx.x];
    if (threadIdx.x < NCLS) bs[threadIdx.x] = g_b1f[threadIdx.x];
    __syncthreads();
    int node = blockIdx.x * blockDim.x + threadIdx.x;
    if (node >= NN) return;
    float l0 = bs[0], l1 = bs[1], l2 = bs[2], l3 = bs[3];
#pragma unroll 8
    for (int k = 0; k < CC; k++) {
        float h = g_h[node * CC + k];
        l0 += h * Ws[k * 4 + 0];
        l1 += h * Ws[k * 4 + 1];
        l2 += h * Ws[k * 4 + 2];
        l3 += h * Ws[k * 4 + 3];
    }
    float m = fmaxf(fmaxf(l0, l1), fmaxf(l2, l3));
    float s = __expf(l0 - m) + __expf(l1 - m) + __expf(l2 - m) + __expf(l3 - m);
    float ls = m + __logf(s);
    float4 o;
    o.x = l0 - ls; o.y = l1 - ls; o.z = l2 - ls; o.w = l3 - ls;
    *(float4*)(out + node * 4) = o;
}

// ---------------- launcher ----------------
extern "C" void kernel_launch(void* const* d_in, const int* in_sizes, int n_in,
                              void* d_out, int out_size) {
    const float* x     = (const float*)d_in[0];
    const int*   ei    = (const int*)d_in[1];
    const float* Wl1   = (const float*)d_in[2];
    const float* bl1   = (const float*)d_in[3];
    const float* Wr1   = (const float*)d_in[4];
    const float* br1   = (const float*)d_in[5];
    const float* att1  = (const float*)d_in[6];
    const float* bias1 = (const float*)d_in[7];
    const float* gng1  = (const float*)d_in[8];
    const float* gnb1  = (const float*)d_in[9];
    const float* gna1  = (const float*)d_in[10];
    const float* Wl2   = (const float*)d_in[11];
    const float* bl2   = (const float*)d_in[12];
    const float* Wr2   = (const float*)d_in[13];
    const float* br2   = (const float*)d_in[14];
    const float* att2  = (const float*)d_in[15];
    const float* bias2 = (const float*)d_in[16];
    const float* gng2  = (const float*)d_in[17];
    const float* gnb2  = (const float*)d_in[18];
    const float* gna2  = (const float*)d_in[19];
    const float* W1    = (const float*)d_in[20];
    const float* b1    = (const float*)d_in[21];
    float* out = (float*)d_out;

    float *p_xr, *p_h, *p_blf, *p_brf;
    __half *p_xlh;
    __nv_bfloat16 *p_Ah, *p_Al, *p_Blh, *p_Bll, *p_Brh, *p_Brl;
    cudaGetSymbolAddress((void**)&p_xlh, g_xlh);
    cudaGetSymbolAddress((void**)&p_xr,  g_xr);
    cudaGetSymbolAddress((void**)&p_h,   g_h);
    cudaGetSymbolAddress((void**)&p_blf, g_blf);
    cudaGetSymbolAddress((void**)&p_brf, g_brf);
    cudaGetSymbolAddress((void**)&p_Ah,  g_Ah);
    cudaGetSymbolAddress((void**)&p_Al,  g_Al);
    cudaGetSymbolAddress((void**)&p_Blh, g_Blh);
    cudaGetSymbolAddress((void**)&p_Bll, g_Bll);
    cudaGetSymbolAddress((void**)&p_Brh, g_Brh);
    cudaGetSymbolAddress((void**)&p_Brl, g_Brl);

    cudaFuncSetAttribute(k_mma_gemm<128>, cudaFuncAttributeMaxDynamicSharedMemorySize, SMEM_TOT);
    cudaFuncSetAttribute(k_mma_gemm<64>,  cudaFuncAttributeMaxDynamicSharedMemorySize, SMEM_TOT);

    const int TB = 256;
    const int TA = 128;                         /* attn block: smaller straggler */
    int gN   = (NN + TB - 1) / TB;
    int gC4  = (EE / 4 + TB - 1) / TB;
    int gS4  = (EE / 4 + (NN + 3) / 4 + TB - 1) / TB;
    int gNw  = (NN * 32 + TA - 1) / TA;
    int gCX  = (PADN * 32 + TB - 1) / TB;
    int gCW  = (2 * HC * HC + TB - 1) / TB;
    dim3 gG(GEMM_CTAS, 2);

    k_zero_deg<<<gN, TB>>>();                                          // 0
    k_conv_x<<<gCX, TB>>>(x);                                          // 1
    k_conv_w1<<<gCW, TB>>>(Wl1, Wr1);                                  // 2
    k_mma_gemm<128><<<gG, 256, SMEM_TOT>>>(                            // 3 (profiled)
        p_Ah, p_Al, p_Blh, p_Bll, p_Brh, p_Brl, bl1, br1, p_xlh, p_xr);
    k_count<<<gC4, TB>>>(ei);                                          // 4
    k_scan_chained<<<SCAN_NB, SCAN_B>>>();                             // 5
    k_scatter<<<gS4, TB>>>(ei);                                        // 6

    // ---- layer 1 aggregation ----
    k_attn_agg<<<gNw, TA>>>(p_xlh, p_xr, att1, bias1);                 // 7
    k_finalize_fold2<<<1, 256>>>(gng1, gnb1, gna1, Wl2, bl2, Wr2, br2);

    // ---- layer 2 ----
    k_mma_gemm<64><<<gG, 256, SMEM_TOT>>>(
        p_Ah, p_Al, p_Blh, p_Bll, p_Brh, p_Brl, p_blf, p_brf, p_xlh, p_xr);
    k_attn_agg<<<gNw, TA>>>(p_xlh, p_xr, att2, bias2);
    k_finalize_fold_final<<<1, 64>>>(gng2, gnb2, gna2, W1, b1);

    k_classify<<<gN, TB>>>(out);
}